// round 14
// baseline (speedup 1.0000x reference)
#include <cuda_runtime.h>
#include <cuda_fp16.h>
#include <cstdint>

#define NN 50000
#define EE 600000
#define GG 256
#define HH 128
#define SCAN_B 512
#define NP ((NN + SCAN_B - 1) / SCAN_B)   // 98

// ---------------- scratch ----------------
__device__ __half g_x16[NN * HH];     // fp16 activations (GEMM input)
__device__ __half g_tmp[NN * HH];     // fp16 GEMM output
__device__ __half g_wh[3 * HH * HH];  // fp16 weights hi  [k][n]
__device__ __half g_wl[3 * HH * HH];  // fp16 weights lo  [k][n]
__device__ float g_dis[NN];
__device__ int   g_deg[NN];
__device__ int   g_row_off[NN + 1];
__device__ int   g_fill[NN];
__device__ int2  g_edge[EE];          // packed (src, __float_as_int(norm))
__device__ float g_cnt[GG];           // nodes per graph (bisection on sorted batch_idx)
__device__ int   g_part[NP];
__device__ int   g_idx64;

__device__ __forceinline__ int idx_at(const void* p, long long i) {
    if (g_idx64) return (int)((const long long*)p)[i];
    return ((const int*)p)[i];
}

__device__ __forceinline__ int roff(int j) {
    if (j == 0) return 0;
    int b = (j - 1) / SCAN_B;
    int v = g_row_off[j];
    return (b > 0) ? v + g_part[b - 1] : v;
}

// ---------------- init: detect dtype, zero, graph counts via bisection ----------------
__global__ void init_kernel(float* __restrict__ out, const int* __restrict__ ei_raw,
                            const void* __restrict__ bidx) {
    __shared__ int s_is64;
    int i = blockIdx.x * blockDim.x + threadIdx.x;
    if (blockIdx.x == 0) {
        if (threadIdx.x == 0) {
            int all_zero = 1;
            for (int k = 1; k < 64; k += 2)
                if (ei_raw[k] != 0) all_zero = 0;
            g_idx64 = all_zero;
            s_is64 = all_zero;
        }
        __syncthreads();
        int is64 = s_is64;
        if (threadIdx.x < GG) {
            int g = threadIdx.x;
            int lo = 0, hi = NN;
            while (lo < hi) {
                int mid = (lo + hi) >> 1;
                int v = is64 ? (int)((const long long*)bidx)[mid] : ((const int*)bidx)[mid];
                if (v < g) lo = mid + 1; else hi = mid;
            }
            int start = lo;
            lo = 0; hi = NN;
            int g1 = g + 1;
            while (lo < hi) {
                int mid = (lo + hi) >> 1;
                int v = is64 ? (int)((const long long*)bidx)[mid] : ((const int*)bidx)[mid];
                if (v < g1) lo = mid + 1; else hi = mid;
            }
            g_cnt[g] = (float)(lo - start);
        }
    }
    if (i < NN) { g_deg[i] = 0; g_fill[i] = 0; }
    if (i < GG * HH) out[i] = 0.0f;
}

// ---------------- merged: x->fp16, W->fp16 hi/lo, deg histogram ----------------
__global__ void cvt_deg_kernel(const float* __restrict__ x,
                               const float* __restrict__ W1,
                               const float* __restrict__ W2,
                               const float* __restrict__ W3,
                               const void* __restrict__ edge_index) {
    int i = blockIdx.x * blockDim.x + threadIdx.x;
    if (i < NN * HH / 4) {
        float4 v = ((const float4*)x)[i];
        __half2* p = (__half2*)&g_x16[i * 4];
        p[0] = __floats2half2_rn(v.x, v.y);
        p[1] = __floats2half2_rn(v.z, v.w);
    }
    if (i < 3 * HH * HH) {
        int which = i >> 14;
        int j = i & (HH * HH - 1);
        const float* W = (which == 0) ? W1 : (which == 1) ? W2 : W3;
        float w = W[j];
        __half h = __float2half_rn(w);
        g_wh[i] = h;
        g_wl[i] = __float2half_rn(w - __half2float(h));
    }
    if (i < EE) {
        atomicAdd(&g_deg[idx_at(edge_index, (long long)EE + i)], 1);
    }
}

// ---------------- scan phase 1 (+ deg_inv_sqrt fused) ----------------
__global__ void scan1_kernel() {
    __shared__ int wsum[16];
    int b = blockIdx.x, t = threadIdx.x;
    int i = b * SCAN_B + t;
    int lane = t & 31, w = t >> 5;
    int v = (i < NN) ? g_deg[i] : 0;
    if (i < NN) g_dis[i] = rsqrtf((float)v + 1.0f);
    int x = v;
    #pragma unroll
    for (int off = 1; off < 32; off <<= 1) {
        int y = __shfl_up_sync(0xffffffffu, x, off);
        if (lane >= off) x += y;
    }
    if (lane == 31) wsum[w] = x;
    __syncthreads();
    if (w == 0) {
        int s = (lane < 16) ? wsum[lane] : 0;
        #pragma unroll
        for (int off = 1; off < 16; off <<= 1) {
            int y = __shfl_up_sync(0xffffffffu, s, off);
            if (lane >= off) s += y;
        }
        if (lane < 16) wsum[lane] = s;
    }
    __syncthreads();
    int inc = x + ((w > 0) ? wsum[w - 1] : 0);
    if (i < NN) g_row_off[i + 1] = inc;
    if (t == SCAN_B - 1) g_part[b] = inc;
}

__global__ void scan2_kernel() {
    __shared__ int wsum[4];
    int t = threadIdx.x;
    int lane = t & 31, w = t >> 5;
    int x = (t < NP) ? g_part[t] : 0;
    #pragma unroll
    for (int off = 1; off < 32; off <<= 1) {
        int y = __shfl_up_sync(0xffffffffu, x, off);
        if (lane >= off) x += y;
    }
    if (lane == 31) wsum[w] = x;
    __syncthreads();
    if (w == 0 && lane < 4) {
        int s = wsum[lane];
        #pragma unroll
        for (int off = 1; off < 4; off <<= 1) {
            int y = __shfl_up_sync(0x0000000fu, s, off);
            if (lane >= off) s += y;
        }
        wsum[lane] = s;
    }
    __syncthreads();
    int inc = x + ((w > 0) ? wsum[w - 1] : 0);
    if (t < NP) g_part[t] = inc;
}

// ---------------- CSR fill: 2 edges/thread for ILP ----------------
__global__ void fill_kernel(const void* __restrict__ edge_index) {
    int e0 = (blockIdx.x * blockDim.x + threadIdx.x) * 2;
    if (e0 >= EE) return;
    int e1 = e0 + 1;
    bool has1 = e1 < EE;

    int s0 = idx_at(edge_index, e0);
    int d0 = idx_at(edge_index, (long long)EE + e0);
    int s1v = 0, d1v = 0;
    if (has1) {
        s1v = idx_at(edge_index, e1);
        d1v = idx_at(edge_index, (long long)EE + e1);
    }
    int p0 = roff(d0) + atomicAdd(&g_fill[d0], 1);
    int p1 = 0;
    if (has1) p1 = roff(d1v) + atomicAdd(&g_fill[d1v], 1);

    g_edge[p0] = make_int2(s0, __float_as_int(g_dis[s0] * g_dis[d0]));
    if (has1) g_edge[p1] = make_int2(s1v, __float_as_int(g_dis[s1v] * g_dis[d1v]));
}

// ---------------- mma helpers ----------------
__device__ __forceinline__ uint32_t smem_u32(const void* p) {
    return (uint32_t)__cvta_generic_to_shared(p);
}
__device__ __forceinline__ void ldsm_x4(uint32_t* r, uint32_t a) {
    asm volatile("ldmatrix.sync.aligned.m8n8.x4.shared.b16 {%0,%1,%2,%3}, [%4];\n"
                 : "=r"(r[0]), "=r"(r[1]), "=r"(r[2]), "=r"(r[3]) : "r"(a));
}
__device__ __forceinline__ void ldsm_x4_t(uint32_t* r, uint32_t a) {
    asm volatile("ldmatrix.sync.aligned.m8n8.x4.trans.shared.b16 {%0,%1,%2,%3}, [%4];\n"
                 : "=r"(r[0]), "=r"(r[1]), "=r"(r[2]), "=r"(r[3]) : "r"(a));
}
__device__ __forceinline__ void mma_f16(float* d, const uint32_t* a, uint32_t b0, uint32_t b1) {
    asm volatile(
        "mma.sync.aligned.m16n8k16.row.col.f32.f16.f16.f32 "
        "{%0,%1,%2,%3}, {%4,%5,%6,%7}, {%8,%9}, {%0,%1,%2,%3};\n"
        : "+f"(d[0]), "+f"(d[1]), "+f"(d[2]), "+f"(d[3])
        : "r"(a[0]), "r"(a[1]), "r"(a[2]), "r"(a[3]), "r"(b0), "r"(b1));
}
__device__ __forceinline__ void cp16(uint32_t dst, const void* src, int srcsize) {
    asm volatile("cp.async.cg.shared.global [%0], [%1], 16, %2;\n"
                 :: "r"(dst), "l"(src), "r"(srcsize));
}

// ---------------- fp16 2-term GEMM: 64-row tiles, 128 threads, double-buffered ----------------
#define KC 32
#define TM 64
#define A_PITCH 40
#define W_PITCH 136
#define SA_BYTES (TM * A_PITCH * 2)                  // 5120
#define SW_BYTES (KC * W_PITCH * 2)                  // 8704
#define STAGE_BYTES (SA_BYTES + 2 * SW_BYTES)        // 22528
#define GEMM_SMEM (2 * STAGE_BYTES)                  // 45056

__global__ __launch_bounds__(128) void gemm_f16_kernel(
    const __half* __restrict__ A,
    const __half* __restrict__ Wh, const __half* __restrict__ Wl,
    __half* __restrict__ C, int M)
{
    extern __shared__ char smem[];
    int tid = threadIdx.x;
    int wid = tid >> 5, lane = tid & 31;
    int wm = wid & 1, wn = wid >> 1;     // 2x2 warp grid, warp tile 32x64
    int m0 = blockIdx.x * TM;

    auto sA  = [&](int s) -> __half* { return (__half*)(smem + s * STAGE_BYTES); };
    auto sWh = [&](int s) -> __half* { return (__half*)(smem + s * STAGE_BYTES + SA_BYTES); };
    auto sWl = [&](int s) -> __half* { return (__half*)(smem + s * STAGE_BYTES + SA_BYTES + SW_BYTES); };

    auto prefetch = [&](int s, int k0) {
        #pragma unroll
        for (int it = 0; it < 2; it++) {
            int slot = tid + it * 128;          // 256: 64 rows x 4 chunks
            int row = slot >> 2, q = slot & 3;
            int m = m0 + row;
            cp16(smem_u32(sA(s) + row * A_PITCH + q * 8),
                 &A[(size_t)m * HH + k0 + q * 8], (m < M) ? 16 : 0);
        }
        #pragma unroll
        for (int it = 0; it < 4; it++) {
            int slot = tid + it * 128;          // 512: 32 rows x 16 chunks
            int row = slot >> 4, q = slot & 15;
            cp16(smem_u32(sWh(s) + row * W_PITCH + q * 8), &Wh[(k0 + row) * HH + q * 8], 16);
            cp16(smem_u32(sWl(s) + row * W_PITCH + q * 8), &Wl[(k0 + row) * HH + q * 8], 16);
        }
        asm volatile("cp.async.commit_group;\n");
    };

    float d[2][8][4];
    #pragma unroll
    for (int a = 0; a < 2; a++)
        #pragma unroll
        for (int b = 0; b < 8; b++)
            #pragma unroll
            for (int c = 0; c < 4; c++) d[a][b][c] = 0.0f;

    prefetch(0, 0);

    #pragma unroll
    for (int i = 0; i < 4; i++) {
        asm volatile("cp.async.wait_group 0;\n");
        __syncthreads();
        if (i < 3) prefetch((i + 1) & 1, (i + 1) * KC);

        __half* cA  = sA(i & 1);
        __half* cWh = sWh(i & 1);
        __half* cWl = sWl(i & 1);

        #pragma unroll
        for (int kk = 0; kk < KC; kk += 16) {
            uint32_t af[2][4];
            #pragma unroll
            for (int mi = 0; mi < 2; mi++) {
                int r = wm * 32 + mi * 16 + (lane & 15);
                int c = kk + (lane >> 4) * 8;
                ldsm_x4(af[mi], smem_u32(cA + r * A_PITCH + c));
            }
            #pragma unroll
            for (int ni = 0; ni < 4; ni++) {
                uint32_t bh[4], bl[4];
                int rk = kk + (lane & 15);
                int cn = wn * 64 + ni * 16 + (lane >> 4) * 8;
                ldsm_x4_t(bh, smem_u32(cWh + rk * W_PITCH + cn));
                ldsm_x4_t(bl, smem_u32(cWl + rk * W_PITCH + cn));
                #pragma unroll
                for (int mi = 0; mi < 2; mi++) {
                    #pragma unroll
                    for (int h = 0; h < 2; h++) {
                        int nj = ni * 2 + h;
                        mma_f16(d[mi][nj], af[mi], bh[h*2], bh[h*2+1]);
                        mma_f16(d[mi][nj], af[mi], bl[h*2], bl[h*2+1]);
                    }
                }
            }
        }
        __syncthreads();
    }

    #pragma unroll
    for (int mi = 0; mi < 2; mi++) {
        #pragma unroll
        for (int nj = 0; nj < 8; nj++) {
            int col = wn * 64 + nj * 8 + (lane & 3) * 2;
            int r0 = m0 + wm * 32 + mi * 16 + (lane >> 2);
            if (r0 < M)
                *(__half2*)&C[(size_t)r0 * HH + col] = __floats2half2_rn(d[mi][nj][0], d[mi][nj][1]);
            int r1 = r0 + 8;
            if (r1 < M)
                *(__half2*)&C[(size_t)r1 * HH + col] = __floats2half2_rn(d[mi][nj][2], d[mi][nj][3]);
        }
    }
}

// ---------------- aggregation (one warp/node, packed edges, scaled pool) ----------------
__device__ __forceinline__ float4 ld_row_h(const __half* h, int node, int lane) {
    float2 r = *(const float2*)&h[(size_t)node * HH + lane * 4];
    __half2 a = *(__half2*)&r.x;
    __half2 b = *(__half2*)&r.y;
    float2 fa = __half22float2(a), fb = __half22float2(b);
    return make_float4(fa.x, fa.y, fb.x, fb.y);
}

__global__ void agg_kernel(const __half* __restrict__ h,
                           const float* __restrict__ bias,
                           __half* __restrict__ out16,
                           int do_pool,
                           const void* __restrict__ batch_idx,
                           float* __restrict__ pool)
{
    int warp = (blockIdx.x * blockDim.x + threadIdx.x) >> 5;
    int lane = threadIdx.x & 31;
    if (warp >= NN) return;
    int n = warp;

    float dn = g_dis[n];
    float self = dn * dn;

    float4 acc = ld_row_h(h, n, lane);
    acc.x *= self; acc.y *= self; acc.z *= self; acc.w *= self;

    int e  = roff(n);
    int s1 = roff(n + 1);
    for (; e + 3 < s1; e += 4) {
        int2 eA = g_edge[e],   eB = g_edge[e+1];
        int2 eC = g_edge[e+2], eD = g_edge[e+3];
        float nA = __int_as_float(eA.y), nB = __int_as_float(eB.y);
        float nC = __int_as_float(eC.y), nD = __int_as_float(eD.y);
        float4 vA = ld_row_h(h, eA.x, lane);
        float4 vB = ld_row_h(h, eB.x, lane);
        float4 vC = ld_row_h(h, eC.x, lane);
        float4 vD = ld_row_h(h, eD.x, lane);
        acc.x += vA.x*nA + vB.x*nB + vC.x*nC + vD.x*nD;
        acc.y += vA.y*nA + vB.y*nB + vC.y*nC + vD.y*nD;
        acc.z += vA.z*nA + vB.z*nB + vC.z*nC + vD.z*nD;
        acc.w += vA.w*nA + vB.w*nB + vC.w*nC + vD.w*nD;
    }
    for (; e < s1; e++) {
        int2 ed = g_edge[e];
        float nrm = __int_as_float(ed.y);
        float4 v  = ld_row_h(h, ed.x, lane);
        acc.x += v.x * nrm; acc.y += v.y * nrm;
        acc.z += v.z * nrm; acc.w += v.w * nrm;
    }

    float4 bb = *reinterpret_cast<const float4*>(&bias[lane * 4]);
    acc.x = fmaxf(acc.x + bb.x, 0.0f);
    acc.y = fmaxf(acc.y + bb.y, 0.0f);
    acc.z = fmaxf(acc.z + bb.z, 0.0f);
    acc.w = fmaxf(acc.w + bb.w, 0.0f);

    if (!do_pool) {
        __half2* p = (__half2*)&out16[(size_t)n * HH + lane * 4];
        p[0] = __floats2half2_rn(acc.x, acc.y);
        p[1] = __floats2half2_rn(acc.z, acc.w);
    } else {
        int g = idx_at(batch_idx, n);
        float ic = 1.0f / fmaxf(g_cnt[g], 1.0f);
        float* p = &pool[g * HH + lane * 4];
        atomicAdd(p + 0, acc.x * ic);
        atomicAdd(p + 1, acc.y * ic);
        atomicAdd(p + 2, acc.z * ic);
        atomicAdd(p + 3, acc.w * ic);
    }
}

// ---------------- launch ----------------
extern "C" void kernel_launch(void* const* d_in, const int* in_sizes, int n_in,
                              void* d_out, int out_size)
{
    const float* x    = (const float*)d_in[0];
    const float* W1   = (const float*)d_in[1];
    const float* b1   = (const float*)d_in[2];
    const float* W2   = (const float*)d_in[3];
    const float* b2   = (const float*)d_in[4];
    const float* W3   = (const float*)d_in[5];
    const float* b3   = (const float*)d_in[6];
    const void*  ei   = d_in[7];
    const void*  bidx = d_in[8];
    float* out = (float*)d_out;

    __half *x16, *tmp, *wh, *wl;
    cudaGetSymbolAddress((void**)&x16, g_x16);
    cudaGetSymbolAddress((void**)&tmp, g_tmp);
    cudaGetSymbolAddress((void**)&wh,  g_wh);
    cudaGetSymbolAddress((void**)&wl,  g_wl);
    (void)in_sizes; (void)n_in; (void)out_size;

    static int attr_set = 0;
    if (!attr_set) {
        cudaFuncSetAttribute(gemm_f16_kernel,
                             cudaFuncAttributeMaxDynamicSharedMemorySize, GEMM_SMEM);
        attr_set = 1;
    }

    const int T = 256;
    int gemm_blocks = (NN + TM - 1) / TM;            // 782
    int agg_blocks  = (NN * 32 + T - 1) / T;
    int cvt_blocks  = (NN * HH / 4 + T - 1) / T;
    int fill_blocks = (EE / 2 + T - 1) / T;

    // gemm1 at local index 3 => ncu (-s 5, harness offset ~2) profiles it
    init_kernel<<<(NN + T - 1) / T, T>>>(out, (const int*)ei, bidx);              // 0
    cvt_deg_kernel<<<cvt_blocks, T>>>(x, W1, W2, W3, ei);                         // 1
    scan1_kernel<<<NP, SCAN_B>>>();                                               // 2
    gemm_f16_kernel<<<gemm_blocks, 128, GEMM_SMEM>>>(x16, wh, wl, tmp, NN);       // 3 (profiled)
    scan2_kernel<<<1, 128>>>();                                                   // 4
    fill_kernel<<<fill_blocks, T>>>(ei);                                          // 5
    agg_kernel<<<agg_blocks, T>>>(tmp, b1, x16, 0, bidx, out);                    // 6

    gemm_f16_kernel<<<gemm_blocks, 128, GEMM_SMEM>>>(x16, wh + HH*HH, wl + HH*HH, tmp, NN);
    agg_kernel<<<agg_blocks, T>>>(tmp, b2, x16, 0, bidx, out);

    gemm_f16_kernel<<<gemm_blocks, 128, GEMM_SMEM>>>(x16, wh + 2*HH*HH, wl + 2*HH*HH, tmp, NN);
    agg_kernel<<<agg_blocks, T>>>(tmp, b3, x16, 1, bidx, out);
}

// round 15
// speedup vs baseline: 1.0562x; 1.0562x over previous
#include <cuda_runtime.h>
#include <cuda_fp16.h>
#include <cstdint>

#define NN 50000
#define EE 600000
#define GG 256
#define HH 128
#define SCAN_B 512
#define NP ((NN + SCAN_B - 1) / SCAN_B)   // 98

// ---------------- scratch ----------------
__device__ __half g_x16[NN * HH];
__device__ __half g_tmp[NN * HH];
__device__ __half g_wh[3 * HH * HH];
__device__ __half g_wl[3 * HH * HH];
__device__ float g_dis[NN];
__device__ int   g_deg[NN];
__device__ int   g_row_off[NN + 1];
__device__ int   g_fill[NN];
__device__ int2  g_edge[EE];
__device__ float g_cnt[GG];
__device__ int   g_part[NP];
__device__ int   g_idx64;

__device__ __forceinline__ int idx_at(const void* p, long long i) {
    if (g_idx64) return (int)((const long long*)p)[i];
    return ((const int*)p)[i];
}

__device__ __forceinline__ int roff(int j) {
    if (j == 0) return 0;
    int b = (j - 1) / SCAN_B;
    int v = g_row_off[j];
    return (b > 0) ? v + g_part[b - 1] : v;
}

// ---------------- init: detect dtype, zero, graph counts via bisection ----------------
__global__ void init_kernel(float* __restrict__ out, const int* __restrict__ ei_raw,
                            const void* __restrict__ bidx) {
    __shared__ int s_is64;
    int i = blockIdx.x * blockDim.x + threadIdx.x;
    if (blockIdx.x == 0) {
        if (threadIdx.x == 0) {
            int all_zero = 1;
            for (int k = 1; k < 64; k += 2)
                if (ei_raw[k] != 0) all_zero = 0;
            g_idx64 = all_zero;
            s_is64 = all_zero;
        }
        __syncthreads();
        int is64 = s_is64;
        if (threadIdx.x < GG) {
            int g = threadIdx.x;
            int lo = 0, hi = NN;
            while (lo < hi) {
                int mid = (lo + hi) >> 1;
                int v = is64 ? (int)((const long long*)bidx)[mid] : ((const int*)bidx)[mid];
                if (v < g) lo = mid + 1; else hi = mid;
            }
            int start = lo;
            lo = 0; hi = NN;
            int g1 = g + 1;
            while (lo < hi) {
                int mid = (lo + hi) >> 1;
                int v = is64 ? (int)((const long long*)bidx)[mid] : ((const int*)bidx)[mid];
                if (v < g1) lo = mid + 1; else hi = mid;
            }
            g_cnt[g] = (float)(lo - start);
        }
    }
    if (i < NN) { g_deg[i] = 0; g_fill[i] = 0; }
    if (i < GG * HH) out[i] = 0.0f;
}

// ---------------- convert only: x->fp16, W->fp16 hi/lo (stream A) ----------------
__global__ void cvt_kernel(const float* __restrict__ x,
                           const float* __restrict__ W1,
                           const float* __restrict__ W2,
                           const float* __restrict__ W3) {
    int i = blockIdx.x * blockDim.x + threadIdx.x;
    if (i < NN * HH / 4) {
        float4 v = ((const float4*)x)[i];
        __half2* p = (__half2*)&g_x16[i * 4];
        p[0] = __floats2half2_rn(v.x, v.y);
        p[1] = __floats2half2_rn(v.z, v.w);
    }
    if (i < 3 * HH * HH) {
        int which = i >> 14;
        int j = i & (HH * HH - 1);
        const float* W = (which == 0) ? W1 : (which == 1) ? W2 : W3;
        float w = W[j];
        __half h = __float2half_rn(w);
        g_wh[i] = h;
        g_wl[i] = __float2half_rn(w - __half2float(h));
    }
}

// ---------------- degree histogram (stream B) ----------------
__global__ void deg_kernel(const void* __restrict__ edge_index) {
    int e = blockIdx.x * blockDim.x + threadIdx.x;
    if (e >= EE) return;
    atomicAdd(&g_deg[idx_at(edge_index, (long long)EE + e)], 1);
}

// ---------------- scan phase 1 (+ deg_inv_sqrt fused) ----------------
__global__ void scan1_kernel() {
    __shared__ int wsum[16];
    int b = blockIdx.x, t = threadIdx.x;
    int i = b * SCAN_B + t;
    int lane = t & 31, w = t >> 5;
    int v = (i < NN) ? g_deg[i] : 0;
    if (i < NN) g_dis[i] = rsqrtf((float)v + 1.0f);
    int x = v;
    #pragma unroll
    for (int off = 1; off < 32; off <<= 1) {
        int y = __shfl_up_sync(0xffffffffu, x, off);
        if (lane >= off) x += y;
    }
    if (lane == 31) wsum[w] = x;
    __syncthreads();
    if (w == 0) {
        int s = (lane < 16) ? wsum[lane] : 0;
        #pragma unroll
        for (int off = 1; off < 16; off <<= 1) {
            int y = __shfl_up_sync(0xffffffffu, s, off);
            if (lane >= off) s += y;
        }
        if (lane < 16) wsum[lane] = s;
    }
    __syncthreads();
    int inc = x + ((w > 0) ? wsum[w - 1] : 0);
    if (i < NN) g_row_off[i + 1] = inc;
    if (t == SCAN_B - 1) g_part[b] = inc;
}

__global__ void scan2_kernel() {
    __shared__ int wsum[4];
    int t = threadIdx.x;
    int lane = t & 31, w = t >> 5;
    int x = (t < NP) ? g_part[t] : 0;
    #pragma unroll
    for (int off = 1; off < 32; off <<= 1) {
        int y = __shfl_up_sync(0xffffffffu, x, off);
        if (lane >= off) x += y;
    }
    if (lane == 31) wsum[w] = x;
    __syncthreads();
    if (w == 0 && lane < 4) {
        int s = wsum[lane];
        #pragma unroll
        for (int off = 1; off < 4; off <<= 1) {
            int y = __shfl_up_sync(0x0000000fu, s, off);
            if (lane >= off) s += y;
        }
        wsum[lane] = s;
    }
    __syncthreads();
    int inc = x + ((w > 0) ? wsum[w - 1] : 0);
    if (t < NP) g_part[t] = inc;
}

// ---------------- CSR fill: 2 edges/thread ----------------
__global__ void fill_kernel(const void* __restrict__ edge_index) {
    int e0 = (blockIdx.x * blockDim.x + threadIdx.x) * 2;
    if (e0 >= EE) return;
    int e1 = e0 + 1;
    bool has1 = e1 < EE;

    int s0 = idx_at(edge_index, e0);
    int d0 = idx_at(edge_index, (long long)EE + e0);
    int s1v = 0, d1v = 0;
    if (has1) {
        s1v = idx_at(edge_index, e1);
        d1v = idx_at(edge_index, (long long)EE + e1);
    }
    int p0 = roff(d0) + atomicAdd(&g_fill[d0], 1);
    int p1 = 0;
    if (has1) p1 = roff(d1v) + atomicAdd(&g_fill[d1v], 1);

    g_edge[p0] = make_int2(s0, __float_as_int(g_dis[s0] * g_dis[d0]));
    if (has1) g_edge[p1] = make_int2(s1v, __float_as_int(g_dis[s1v] * g_dis[d1v]));
}

// ---------------- mma helpers ----------------
__device__ __forceinline__ uint32_t smem_u32(const void* p) {
    return (uint32_t)__cvta_generic_to_shared(p);
}
__device__ __forceinline__ void ldsm_x4(uint32_t* r, uint32_t a) {
    asm volatile("ldmatrix.sync.aligned.m8n8.x4.shared.b16 {%0,%1,%2,%3}, [%4];\n"
                 : "=r"(r[0]), "=r"(r[1]), "=r"(r[2]), "=r"(r[3]) : "r"(a));
}
__device__ __forceinline__ void ldsm_x4_t(uint32_t* r, uint32_t a) {
    asm volatile("ldmatrix.sync.aligned.m8n8.x4.trans.shared.b16 {%0,%1,%2,%3}, [%4];\n"
                 : "=r"(r[0]), "=r"(r[1]), "=r"(r[2]), "=r"(r[3]) : "r"(a));
}
__device__ __forceinline__ void mma_f16(float* d, const uint32_t* a, uint32_t b0, uint32_t b1) {
    asm volatile(
        "mma.sync.aligned.m16n8k16.row.col.f32.f16.f16.f32 "
        "{%0,%1,%2,%3}, {%4,%5,%6,%7}, {%8,%9}, {%0,%1,%2,%3};\n"
        : "+f"(d[0]), "+f"(d[1]), "+f"(d[2]), "+f"(d[3])
        : "r"(a[0]), "r"(a[1]), "r"(a[2]), "r"(a[3]), "r"(b0), "r"(b1));
}
__device__ __forceinline__ void cp16(uint32_t dst, const void* src, int srcsize) {
    asm volatile("cp.async.cg.shared.global [%0], [%1], 16, %2;\n"
                 :: "r"(dst), "l"(src), "r"(srcsize));
}

// ---------------- fp16 2-term GEMM (R13 config: 128-row tiles, double-buffered) ----------------
#define KC 32
#define A_PITCH 40
#define W_PITCH 136
#define SA_BYTES (128 * A_PITCH * 2)                 // 10240
#define SW_BYTES (KC * W_PITCH * 2)                  // 8704
#define STAGE_BYTES (SA_BYTES + 2 * SW_BYTES)        // 27648
#define GEMM_SMEM (2 * STAGE_BYTES)                  // 55296

__global__ __launch_bounds__(256) void gemm_f16_kernel(
    const __half* __restrict__ A,
    const __half* __restrict__ Wh, const __half* __restrict__ Wl,
    __half* __restrict__ C, int M)
{
    extern __shared__ char smem[];
    int tid = threadIdx.x;
    int wid = tid >> 5, lane = tid & 31;
    int wm = wid & 3, wn = wid >> 2;
    int m0 = blockIdx.x * 128;

    auto sA  = [&](int s) -> __half* { return (__half*)(smem + s * STAGE_BYTES); };
    auto sWh = [&](int s) -> __half* { return (__half*)(smem + s * STAGE_BYTES + SA_BYTES); };
    auto sWl = [&](int s) -> __half* { return (__half*)(smem + s * STAGE_BYTES + SA_BYTES + SW_BYTES); };

    auto prefetch = [&](int s, int k0) {
        #pragma unroll
        for (int it = 0; it < 2; it++) {
            int slot = tid + it * 256;
            int row = slot >> 2, q = slot & 3;
            int m = m0 + row;
            cp16(smem_u32(sA(s) + row * A_PITCH + q * 8),
                 &A[(size_t)m * HH + k0 + q * 8], (m < M) ? 16 : 0);
        }
        #pragma unroll
        for (int it = 0; it < 2; it++) {
            int slot = tid + it * 256;
            int row = slot >> 4, q = slot & 15;
            cp16(smem_u32(sWh(s) + row * W_PITCH + q * 8), &Wh[(k0 + row) * HH + q * 8], 16);
            cp16(smem_u32(sWl(s) + row * W_PITCH + q * 8), &Wl[(k0 + row) * HH + q * 8], 16);
        }
        asm volatile("cp.async.commit_group;\n");
    };

    float d[2][8][4];
    #pragma unroll
    for (int a = 0; a < 2; a++)
        #pragma unroll
        for (int b = 0; b < 8; b++)
            #pragma unroll
            for (int c = 0; c < 4; c++) d[a][b][c] = 0.0f;

    prefetch(0, 0);

    #pragma unroll
    for (int i = 0; i < 4; i++) {
        asm volatile("cp.async.wait_group 0;\n");
        __syncthreads();
        if (i < 3) prefetch((i + 1) & 1, (i + 1) * KC);

        __half* cA  = sA(i & 1);
        __half* cWh = sWh(i & 1);
        __half* cWl = sWl(i & 1);

        #pragma unroll
        for (int kk = 0; kk < KC; kk += 16) {
            uint32_t af[2][4];
            #pragma unroll
            for (int mi = 0; mi < 2; mi++) {
                int r = wm * 32 + mi * 16 + (lane & 15);
                int c = kk + (lane >> 4) * 8;
                ldsm_x4(af[mi], smem_u32(cA + r * A_PITCH + c));
            }
            #pragma unroll
            for (int ni = 0; ni < 4; ni++) {
                uint32_t bh[4], bl[4];
                int rk = kk + (lane & 15);
                int cn = wn * 64 + ni * 16 + (lane >> 4) * 8;
                ldsm_x4_t(bh, smem_u32(cWh + rk * W_PITCH + cn));
                ldsm_x4_t(bl, smem_u32(cWl + rk * W_PITCH + cn));
                #pragma unroll
                for (int mi = 0; mi < 2; mi++) {
                    #pragma unroll
                    for (int h = 0; h < 2; h++) {
                        int nj = ni * 2 + h;
                        mma_f16(d[mi][nj], af[mi], bh[h*2], bh[h*2+1]);
                        mma_f16(d[mi][nj], af[mi], bl[h*2], bl[h*2+1]);
                    }
                }
            }
        }
        __syncthreads();
    }

    #pragma unroll
    for (int mi = 0; mi < 2; mi++) {
        #pragma unroll
        for (int nj = 0; nj < 8; nj++) {
            int col = wn * 64 + nj * 8 + (lane & 3) * 2;
            int r0 = m0 + wm * 32 + mi * 16 + (lane >> 2);
            if (r0 < M)
                *(__half2*)&C[(size_t)r0 * HH + col] = __floats2half2_rn(d[mi][nj][0], d[mi][nj][1]);
            int r1 = r0 + 8;
            if (r1 < M)
                *(__half2*)&C[(size_t)r1 * HH + col] = __floats2half2_rn(d[mi][nj][2], d[mi][nj][3]);
        }
    }
}

// ---------------- aggregation (one warp/node, packed edges, scaled pool) ----------------
__device__ __forceinline__ float4 ld_row_h(const __half* h, int node, int lane) {
    float2 r = *(const float2*)&h[(size_t)node * HH + lane * 4];
    __half2 a = *(__half2*)&r.x;
    __half2 b = *(__half2*)&r.y;
    float2 fa = __half22float2(a), fb = __half22float2(b);
    return make_float4(fa.x, fa.y, fb.x, fb.y);
}

__global__ void agg_kernel(const __half* __restrict__ h,
                           const float* __restrict__ bias,
                           __half* __restrict__ out16,
                           int do_pool,
                           const void* __restrict__ batch_idx,
                           float* __restrict__ pool)
{
    int warp = (blockIdx.x * blockDim.x + threadIdx.x) >> 5;
    int lane = threadIdx.x & 31;
    if (warp >= NN) return;
    int n = warp;

    float dn = g_dis[n];
    float self = dn * dn;

    float4 acc = ld_row_h(h, n, lane);
    acc.x *= self; acc.y *= self; acc.z *= self; acc.w *= self;

    int e  = roff(n);
    int s1 = roff(n + 1);
    for (; e + 3 < s1; e += 4) {
        int2 eA = g_edge[e],   eB = g_edge[e+1];
        int2 eC = g_edge[e+2], eD = g_edge[e+3];
        float nA = __int_as_float(eA.y), nB = __int_as_float(eB.y);
        float nC = __int_as_float(eC.y), nD = __int_as_float(eD.y);
        float4 vA = ld_row_h(h, eA.x, lane);
        float4 vB = ld_row_h(h, eB.x, lane);
        float4 vC = ld_row_h(h, eC.x, lane);
        float4 vD = ld_row_h(h, eD.x, lane);
        acc.x += vA.x*nA + vB.x*nB + vC.x*nC + vD.x*nD;
        acc.y += vA.y*nA + vB.y*nB + vC.y*nC + vD.y*nD;
        acc.z += vA.z*nA + vB.z*nB + vC.z*nC + vD.z*nD;
        acc.w += vA.w*nA + vB.w*nB + vC.w*nC + vD.w*nD;
    }
    for (; e < s1; e++) {
        int2 ed = g_edge[e];
        float nrm = __int_as_float(ed.y);
        float4 v  = ld_row_h(h, ed.x, lane);
        acc.x += v.x * nrm; acc.y += v.y * nrm;
        acc.z += v.z * nrm; acc.w += v.w * nrm;
    }

    float4 bb = *reinterpret_cast<const float4*>(&bias[lane * 4]);
    acc.x = fmaxf(acc.x + bb.x, 0.0f);
    acc.y = fmaxf(acc.y + bb.y, 0.0f);
    acc.z = fmaxf(acc.z + bb.z, 0.0f);
    acc.w = fmaxf(acc.w + bb.w, 0.0f);

    if (!do_pool) {
        __half2* p = (__half2*)&out16[(size_t)n * HH + lane * 4];
        p[0] = __floats2half2_rn(acc.x, acc.y);
        p[1] = __floats2half2_rn(acc.z, acc.w);
    } else {
        int g = idx_at(batch_idx, n);
        float ic = 1.0f / fmaxf(g_cnt[g], 1.0f);
        float* p = &pool[g * HH + lane * 4];
        atomicAdd(p + 0, acc.x * ic);
        atomicAdd(p + 1, acc.y * ic);
        atomicAdd(p + 2, acc.z * ic);
        atomicAdd(p + 3, acc.w * ic);
    }
}

// ---------------- launch: fork-join streams ----------------
extern "C" void kernel_launch(void* const* d_in, const int* in_sizes, int n_in,
                              void* d_out, int out_size)
{
    const float* x    = (const float*)d_in[0];
    const float* W1   = (const float*)d_in[1];
    const float* b1   = (const float*)d_in[2];
    const float* W2   = (const float*)d_in[3];
    const float* b2   = (const float*)d_in[4];
    const float* W3   = (const float*)d_in[5];
    const float* b3   = (const float*)d_in[6];
    const void*  ei   = d_in[7];
    const void*  bidx = d_in[8];
    float* out = (float*)d_out;

    __half *x16, *tmp, *wh, *wl;
    cudaGetSymbolAddress((void**)&x16, g_x16);
    cudaGetSymbolAddress((void**)&tmp, g_tmp);
    cudaGetSymbolAddress((void**)&wh,  g_wh);
    cudaGetSymbolAddress((void**)&wl,  g_wl);
    (void)in_sizes; (void)n_in; (void)out_size;

    static cudaStream_t sB = nullptr;
    static cudaEvent_t evFork = nullptr, evJoin = nullptr;
    static int once = 0;
    if (!once) {
        cudaFuncSetAttribute(gemm_f16_kernel,
                             cudaFuncAttributeMaxDynamicSharedMemorySize, GEMM_SMEM);
        cudaStreamCreateWithFlags(&sB, cudaStreamNonBlocking);
        cudaEventCreateWithFlags(&evFork, cudaEventDisableTiming);
        cudaEventCreateWithFlags(&evJoin, cudaEventDisableTiming);
        once = 1;
    }

    const int T = 256;
    int gemm_blocks = (NN + 127) / 128;
    int agg_blocks  = (NN * 32 + T - 1) / T;
    int cvt_blocks  = (NN * HH / 4 + T - 1) / T;
    int fill_blocks = (EE / 2 + T - 1) / T;

    // main stream: init -> fork
    init_kernel<<<(NN + T - 1) / T, T>>>(out, (const int*)ei, bidx);
    cudaEventRecord(evFork, 0);

    // stream B: graph build chain
    cudaStreamWaitEvent(sB, evFork, 0);
    deg_kernel<<<(EE + T - 1) / T, T, 0, sB>>>(ei);
    scan1_kernel<<<NP, SCAN_B, 0, sB>>>();
    scan2_kernel<<<1, 128, 0, sB>>>();
    fill_kernel<<<fill_blocks, T, 0, sB>>>(ei);
    cudaEventRecord(evJoin, sB);

    // main stream: convert + gemm1 concurrently with stream B
    cvt_kernel<<<cvt_blocks, T>>>(x, W1, W2, W3);
    gemm_f16_kernel<<<gemm_blocks, 256, GEMM_SMEM>>>(x16, wh, wl, tmp, NN);

    // join, then layer pipeline
    cudaStreamWaitEvent(0, evJoin, 0);
    agg_kernel<<<agg_blocks, T>>>(tmp, b1, x16, 0, bidx, out);

    gemm_f16_kernel<<<gemm_blocks, 256, GEMM_SMEM>>>(x16, wh + HH*HH, wl + HH*HH, tmp, NN);
    agg_kernel<<<agg_blocks, T>>>(tmp, b2, x16, 0, bidx, out);

    gemm_f16_kernel<<<gemm_blocks, 256, GEMM_SMEM>>>(x16, wh + 2*HH*HH, wl + 2*HH*HH, tmp, NN);
    agg_kernel<<<agg_blocks, T>>>(tmp, b3, x16, 1, bidx, out);
}